// round 9
// baseline (speedup 1.0000x reference)
#include <cuda_runtime.h>
#include <cuda_fp16.h>
#include <cstdint>

// ===========================================================================
// GaussProjDrop fused single-launch pipeline (R9).
//   phase U: blocks [0,1024)        : U -> fp16            -> ucnt
//   phase G: blocks [1024,5120)     : gather 4 rows/block  -> gcnt[band]
//   phase M: blocks [5120,7168)     : GEMM CTA (spins on ucnt, gcnt[by]) -> mcnt[by]
//   phase S: blocks [7168,11264)    : scatter 4 rows/block (spins on mcnt[band])
// Dependencies point only at lower block indices -> deadlock-free under
// in-order dispatch. Counters reset by the last scatter block each launch.
// ===========================================================================

namespace {
constexpr int M = 8 * 2048;   // 16384
constexpr int C = 1024;
constexpr float RAND_SCALE = 1.0f / 3.0f;

constexpr int BM = 128, BN = 128, BK = 64;
constexpr int NKT = C / BK;                  // 16
constexpr int STAGES = 3;
constexpr int A_SM_BYTES = BM * BK * 2;      // 16384
constexpr int B_SM_BYTES = BK * BN * 2;      // 16384
constexpr int STAGE_BYTES = A_SM_BYTES + B_SM_BYTES;   // 32768
constexpr int GSMEM = STAGES * STAGE_BYTES;            // 98304 -> 2 CTA/SM

constexpr int NBAND = M / BM;                // 128 row-bands

constexpr int G_U = 1024;                    // uconv blocks
constexpr int G_G = M / 4;                   // 4096 gather blocks
constexpr int G_M = (C / BN) * (M / BM);     // 2048 gemm blocks
constexpr int G_S = M / 4;                   // 4096 scatter blocks
constexpr int OFF_G = G_U;
constexpr int OFF_M = G_U + G_G;
constexpr int OFF_S = G_U + G_G + G_M;
constexpr int GRID  = G_U + G_G + G_M + G_S; // 11264
}

// Scratch (__device__ globals: allocation-free rule)
__device__ __half g_xg[(size_t)M * C];   // gathered x, fp16 (32 MB)
__device__ __half g_uh[(size_t)C * C];   // U, fp16            (2 MB)
__device__ __half g_y [(size_t)M * C];   // y = xg @ U, fp16  (32 MB)

// Pipeline flags (zero-init; reset at end of each launch)
__device__ int gcnt[NBAND];
__device__ int mcnt[NBAND];
__device__ int ucnt;
__device__ int scnt;

// ---------------------------------------------------------------------------
__device__ __forceinline__ void cp_async16(uint32_t dst, const void* src) {
    asm volatile("cp.async.cg.shared.global [%0], [%1], 16;" :: "r"(dst), "l"(src));
}
__device__ __forceinline__ uint32_t smem_u32(const void* p) {
    uint32_t a;
    asm("{ .reg .u64 t; cvta.to.shared.u64 t, %1; cvt.u32.u64 %0, t; }" : "=r"(a) : "l"(p));
    return a;
}
__device__ __forceinline__ void ldsm_x4(uint32_t r[4], uint32_t addr) {
    asm volatile("ldmatrix.sync.aligned.m8n8.x4.shared.b16 {%0,%1,%2,%3}, [%4];"
                 : "=r"(r[0]), "=r"(r[1]), "=r"(r[2]), "=r"(r[3]) : "r"(addr));
}
__device__ __forceinline__ void ldsm_x4_t(uint32_t r[4], uint32_t addr) {
    asm volatile("ldmatrix.sync.aligned.m8n8.x4.trans.shared.b16 {%0,%1,%2,%3}, [%4];"
                 : "=r"(r[0]), "=r"(r[1]), "=r"(r[2]), "=r"(r[3]) : "r"(addr));
}
__device__ __forceinline__ void mma_f16(float c[4], const uint32_t a[4], uint32_t b0, uint32_t b1) {
    asm volatile(
        "mma.sync.aligned.m16n8k16.row.col.f32.f16.f16.f32 "
        "{%0,%1,%2,%3}, {%4,%5,%6,%7}, {%8,%9}, {%0,%1,%2,%3};"
        : "+f"(c[0]), "+f"(c[1]), "+f"(c[2]), "+f"(c[3])
        : "r"(a[0]), "r"(a[1]), "r"(a[2]), "r"(a[3]), "r"(b0), "r"(b1));
}
// Spin until *p >= target (tid0 spins, block-wide release via barrier).
__device__ __forceinline__ void spin_until(int* p, int target) {
    if (threadIdx.x == 0) {
        volatile int* vp = p;
        while (*vp < target) __nanosleep(64);
    }
    __syncthreads();
    __threadfence();
}
// All threads' prior stores globally visible, then tid0 bumps counter.
__device__ __forceinline__ void signal(int* ctr) {
    __threadfence();
    __syncthreads();
    if (threadIdx.x == 0) atomicAdd(ctr, 1);
}

// ---------------------------------------------------------------------------
__device__ __forceinline__ void fill_stage(int f, int tid, uint32_t smb, int by, int bx) {
    const int s = f % STAGES;
    const uint32_t a_base = smb + s * STAGE_BYTES;
    const uint32_t b_base = a_base + A_SM_BYTES;
    const __half* Ag = g_xg + (size_t)(by * BM) * C + f * BK;
    const __half* Bg = g_uh + (size_t)(f * BK) * C + bx * BN;
    #pragma unroll
    for (int i = 0; i < 4; i++) {
        int id = tid + i * 256;
        int r = id >> 3, c = id & 7;
        cp_async16(a_base + r * 128 + ((c ^ (r & 7)) << 4), Ag + (size_t)r * C + c * 8);
    }
    #pragma unroll
    for (int i = 0; i < 4; i++) {
        int id = tid + i * 256;
        int r = id >> 4, c = id & 15;
        cp_async16(b_base + r * 256 + ((c ^ (r & 7)) << 4), Bg + (size_t)r * C + c * 8);
    }
    asm volatile("cp.async.commit_group;" ::: "memory");
}

// ---------------------------------------------------------------------------
__global__ void __launch_bounds__(256, 2)
fused_kernel(const float* __restrict__ x,
             const float* __restrict__ U,
             const int*   __restrict__ perm,
             const int*   __restrict__ randint,
             float*       __restrict__ out) {
    extern __shared__ char smem[];
    const int tid = threadIdx.x;
    const int blk = blockIdx.x;

    // ======================= phase U: U -> fp16 ============================
    if (blk < OFF_G) {
        int i = (blk * 256 + tid) * 4;
        float4 v = *reinterpret_cast<const float4*>(U + i);
        *reinterpret_cast<__half2*>(g_uh + i)     = __floats2half2_rn(v.x, v.y);
        *reinterpret_cast<__half2*>(g_uh + i + 2) = __floats2half2_rn(v.z, v.w);
        signal(&ucnt);
        return;
    }

    // ======================= phase G: gather ===============================
    if (blk < OFF_M) {
        const int g  = blk - OFF_G;           // 0..4095
        const int r0 = g * 4;
        float (*sx)[C] = reinterpret_cast<float (*)[C]>(smem);
        const unsigned mult = ((unsigned)randint[0] * 6u) & 1023u;

        #pragma unroll
        for (int i = 0; i < 4; i++) {
            int id = tid + i * 256;
            int rr = id >> 8, c4 = (id & 255) * 4;
            *reinterpret_cast<float4*>(&sx[rr][c4]) =
                *reinterpret_cast<const float4*>(x + (size_t)(r0 + rr) * C + c4);
        }
        __syncthreads();

        #pragma unroll
        for (int i = 0; i < 8; i++) {
            int id = tid + i * 256;
            int rr = id >> 9, j = (id & 511) * 2;
            unsigned m = (mult * (unsigned)(r0 + rr) + 1u) & 1023u;
            unsigned a0 = ((unsigned)perm[j]     * m) & 1023u;
            unsigned a1 = ((unsigned)perm[j + 1] * m) & 1023u;
            __half2 h = __floats2half2_rn(sx[rr][a0], sx[rr][a1]);
            *reinterpret_cast<__half2*>(g_xg + (size_t)(r0 + rr) * C + j) = h;
        }
        signal(&gcnt[g >> 5]);                // 32 gather blocks per band
        return;
    }

    // ======================= phase M: GEMM =================================
    if (blk < OFF_S) {
        const int q  = blk - OFF_M;
        const int bx = q & 7;                 // 0..7 (fastest, shares A in L2)
        const int by = q >> 3;                // 0..127 band
        const uint32_t smb = smem_u32(smem);

        spin_until(&ucnt, G_U);
        spin_until(&gcnt[by], 32);

        const int wid = tid >> 5, lane = tid & 31;
        const int wm  = wid & 1;
        const int wn  = wid >> 1;
        const int l7   = lane & 7;
        const int seg1 = (lane >> 3) & 1;
        const int seg2 = lane >> 4;

        float acc[4][4][4];
        #pragma unroll
        for (int i = 0; i < 4; i++)
            #pragma unroll
            for (int j = 0; j < 4; j++)
                #pragma unroll
                for (int p = 0; p < 4; p++) acc[i][j][p] = 0.f;

        #pragma unroll
        for (int f = 0; f < STAGES - 1; f++) fill_stage(f, tid, smb, by, bx);

        const int a_rowloc = wm * 64 + l7 + seg1 * 8;
        const int b_kloc   = l7 + seg1 * 8;
        const int b_ccbase = wn * 4 + seg2;

        for (int kt = 0; kt < NKT; kt++) {
            asm volatile("cp.async.wait_group %0;" :: "n"(STAGES - 2) : "memory");
            __syncthreads();

            const int f = kt + STAGES - 1;
            if (f < NKT) fill_stage(f, tid, smb, by, bx);

            const int s = kt % STAGES;
            const uint32_t As = smb + s * STAGE_BYTES;
            const uint32_t Bs = As + A_SM_BYTES;

            #pragma unroll
            for (int ks = 0; ks < 4; ks++) {
                uint32_t afr[4][4], bfr[2][4];
                const int a_chunk = 2 * ks + seg2;
                #pragma unroll
                for (int mt = 0; mt < 4; mt++)
                    ldsm_x4(afr[mt], As + (a_rowloc + mt * 16) * 128 + ((a_chunk ^ l7) << 4));
                const int bk = ks * 16 + b_kloc;
                #pragma unroll
                for (int nb = 0; nb < 2; nb++)
                    ldsm_x4_t(bfr[nb], Bs + bk * 256 + (((b_ccbase + nb * 2) ^ l7) << 4));
                #pragma unroll
                for (int mt = 0; mt < 4; mt++)
                    #pragma unroll
                    for (int nt = 0; nt < 4; nt++)
                        mma_f16(acc[mt][nt], afr[mt],
                                bfr[nt >> 1][2 * (nt & 1)], bfr[nt >> 1][2 * (nt & 1) + 1]);
            }
        }

        const int qid = lane >> 2, tq = lane & 3;
        #pragma unroll
        for (int mt = 0; mt < 4; mt++) {
            const int row = by * BM + wm * 64 + mt * 16 + qid;
            #pragma unroll
            for (int nt = 0; nt < 4; nt++) {
                const int col = bx * BN + wn * 32 + nt * 8 + 2 * tq;
                __half* p0 = g_y + (size_t)row * C + col;
                *reinterpret_cast<__half2*>(p0)         = __floats2half2_rn(acc[mt][nt][0], acc[mt][nt][1]);
                *reinterpret_cast<__half2*>(p0 + 8 * C) = __floats2half2_rn(acc[mt][nt][2], acc[mt][nt][3]);
            }
        }
        signal(&mcnt[by]);                    // 8 gemm blocks per band
        return;
    }

    // ======================= phase S: scatter ==============================
    {
        const int sblk = blk - OFF_S;         // 0..4095
        const int r0   = sblk * 4;
        const int band = sblk >> 5;           // 32 scatter blocks per band

        spin_until(&mcnt[band], 8);

        float (*so)[C] = reinterpret_cast<float (*)[C]>(smem);
        const unsigned mult = ((unsigned)randint[0] * 6u) & 1023u;

        #pragma unroll
        for (int i = 0; i < 8; i++) {
            int id = tid + i * 256;           // 0..2047 half2 chunks (4 rows)
            int rr = id >> 9, j = (id & 511) * 2;
            unsigned m = (mult * (unsigned)(r0 + rr) + 1u) & 1023u;
            float2 v = __half22float2(
                *reinterpret_cast<const __half2*>(g_y + (size_t)(r0 + rr) * C + j));
            so[rr][((unsigned)perm[j]     * m) & 1023u] = v.x;
            so[rr][((unsigned)perm[j + 1] * m) & 1023u] = v.y;
        }
        __syncthreads();

        #pragma unroll
        for (int i = 0; i < 4; i++) {
            int id = tid + i * 256;           // 4 rows x 256 float4
            int rr = id >> 8, j = (id & 255) * 4;
            const size_t off = (size_t)(r0 + rr) * C + j;
            float4 xv = *reinterpret_cast<const float4*>(x + off);
            float4 o;
            o.x = fmaf(so[rr][j],     RAND_SCALE, xv.x);
            o.y = fmaf(so[rr][j + 1], RAND_SCALE, xv.y);
            o.z = fmaf(so[rr][j + 2], RAND_SCALE, xv.z);
            o.w = fmaf(so[rr][j + 3], RAND_SCALE, xv.w);
            *reinterpret_cast<float4*>(out + off) = o;
        }

        // Ticket: last scatter block resets all counters for the next replay.
        __syncthreads();
        if (tid == 0) {
            int old = atomicAdd(&scnt, 1);
            if (old == G_S - 1) {
                for (int i = 0; i < NBAND; i++) { gcnt[i] = 0; mcnt[i] = 0; }
                ucnt = 0;
                scnt = 0;
                __threadfence();
            }
        }
    }
}

// ---------------------------------------------------------------------------
extern "C" void kernel_launch(void* const* d_in, const int* in_sizes, int n_in,
                              void* d_out, int out_size) {
    const float* x       = (const float*)d_in[0];
    const float* U       = (const float*)d_in[1];
    const int*   perm    = (const int*)d_in[2];
    const int*   randint = (const int*)d_in[3];
    float*       out     = (float*)d_out;

    static bool attr_done = false;
    if (!attr_done) {
        cudaFuncSetAttribute(fused_kernel,
                             cudaFuncAttributeMaxDynamicSharedMemorySize, GSMEM);
        attr_done = true;
    }

    fused_kernel<<<GRID, 256, GSMEM>>>(x, U, perm, randint, out);
}

// round 10
// speedup vs baseline: 1.2333x; 1.2333x over previous
#include <cuda_runtime.h>
#include <cuda_fp16.h>
#include <cstdint>

// ===========================================================================
// GaussProjDrop R10: gather (own launch, high occ) ->
//   fused GEMM+scatter launch: each GEMM block, after its band signal,
//   scatters a 16-row slice of band (by - LAG). Tail bands handled by a
//   small appended block range. No numeric change vs R7.
// ===========================================================================

namespace {
constexpr int M = 8 * 2048;   // 16384
constexpr int C = 1024;
constexpr float RAND_SCALE = 1.0f / 3.0f;

constexpr int BM = 128, BN = 128, BK = 64;
constexpr int NKT = C / BK;                  // 16
constexpr int STAGES = 3;
constexpr int A_SM_BYTES = BM * BK * 2;      // 16384
constexpr int B_SM_BYTES = BK * BN * 2;      // 16384
constexpr int STAGE_BYTES = A_SM_BYTES + B_SM_BYTES;   // 32768
constexpr int GSMEM = STAGES * STAGE_BYTES;            // 98304 -> 2 CTA/SM

constexpr int NBAND = M / BM;                // 128
constexpr int LAG   = 32;                    // scatter lag in bands
constexpr int G_M   = (C / BN) * NBAND;      // 2048 GEMM blocks
constexpr int G_T   = LAG * (C / BN);        // 256 tail scatter blocks
constexpr int GRID2 = G_M + G_T;             // 2304
constexpr int TOTAL_SLICES = NBAND * (C / BN);  // 1024

constexpr int GATHER_BLOCKS = M / 4;         // 4096
constexpr int UCONV_BLOCKS  = (C * C) / (256 * 4);  // 1024
}

// Scratch (__device__ globals: allocation-free rule)
__device__ __half g_xg[(size_t)M * C];   // gathered x, fp16 (32 MB)
__device__ __half g_uh[(size_t)C * C];   // U, fp16            (2 MB)
__device__ __half g_y [(size_t)M * C];   // y = xg @ U, fp16  (32 MB)

// Pipeline counters (zero-init; reset by ticket each launch)
__device__ int mcnt[NBAND];
__device__ int scnt;

// ---------------------------------------------------------------------------
__device__ __forceinline__ void cp_async16(uint32_t dst, const void* src) {
    asm volatile("cp.async.cg.shared.global [%0], [%1], 16;" :: "r"(dst), "l"(src));
}
__device__ __forceinline__ uint32_t smem_u32(const void* p) {
    uint32_t a;
    asm("{ .reg .u64 t; cvta.to.shared.u64 t, %1; cvt.u32.u64 %0, t; }" : "=r"(a) : "l"(p));
    return a;
}
__device__ __forceinline__ void ldsm_x4(uint32_t r[4], uint32_t addr) {
    asm volatile("ldmatrix.sync.aligned.m8n8.x4.shared.b16 {%0,%1,%2,%3}, [%4];"
                 : "=r"(r[0]), "=r"(r[1]), "=r"(r[2]), "=r"(r[3]) : "r"(addr));
}
__device__ __forceinline__ void ldsm_x4_t(uint32_t r[4], uint32_t addr) {
    asm volatile("ldmatrix.sync.aligned.m8n8.x4.trans.shared.b16 {%0,%1,%2,%3}, [%4];"
                 : "=r"(r[0]), "=r"(r[1]), "=r"(r[2]), "=r"(r[3]) : "r"(addr));
}
__device__ __forceinline__ void mma_f16(float c[4], const uint32_t a[4], uint32_t b0, uint32_t b1) {
    asm volatile(
        "mma.sync.aligned.m16n8k16.row.col.f32.f16.f16.f32 "
        "{%0,%1,%2,%3}, {%4,%5,%6,%7}, {%8,%9}, {%0,%1,%2,%3};"
        : "+f"(c[0]), "+f"(c[1]), "+f"(c[2]), "+f"(c[3])
        : "r"(a[0]), "r"(a[1]), "r"(a[2]), "r"(a[3]), "r"(b0), "r"(b1));
}
__device__ __forceinline__ void spin_until(int* p, int target) {
    if (threadIdx.x == 0) {
        volatile int* vp = p;
        while (*vp < target) __nanosleep(64);
    }
    __syncthreads();
    __threadfence();
}
__device__ __forceinline__ void signal(int* ctr) {
    __threadfence();
    __syncthreads();
    if (threadIdx.x == 0) atomicAdd(ctr, 1);
}

// ---------------------------------------------------------------------------
// Launch 1 (merged): gather blocks + uconv blocks (R7, proven 19.7us)
// ---------------------------------------------------------------------------
__global__ void __launch_bounds__(256)
gather_uconv_kernel(const float* __restrict__ x,
                    const float* __restrict__ U,
                    const int*   __restrict__ perm,
                    const int*   __restrict__ randint) {
    const int tid = threadIdx.x;

    if (blockIdx.x >= GATHER_BLOCKS) {
        int i = ((blockIdx.x - GATHER_BLOCKS) * 256 + tid) * 4;
        float4 v = *reinterpret_cast<const float4*>(U + i);
        *reinterpret_cast<__half2*>(g_uh + i)     = __floats2half2_rn(v.x, v.y);
        *reinterpret_cast<__half2*>(g_uh + i + 2) = __floats2half2_rn(v.z, v.w);
        return;
    }

    __shared__ float sx[4][C];
    const int r0 = blockIdx.x * 4;
    const unsigned mult = ((unsigned)randint[0] * 6u) & 1023u;

    #pragma unroll
    for (int i = 0; i < 4; i++) {
        int id = tid + i * 256;
        int rr = id >> 8, c4 = (id & 255) * 4;
        *reinterpret_cast<float4*>(&sx[rr][c4]) =
            *reinterpret_cast<const float4*>(x + (size_t)(r0 + rr) * C + c4);
    }
    __syncthreads();

    #pragma unroll
    for (int i = 0; i < 8; i++) {
        int id = tid + i * 256;
        int rr = id >> 9, j = (id & 511) * 2;
        unsigned m = (mult * (unsigned)(r0 + rr) + 1u) & 1023u;
        unsigned a0 = ((unsigned)perm[j]     * m) & 1023u;
        unsigned a1 = ((unsigned)perm[j + 1] * m) & 1023u;
        __half2 h = __floats2half2_rn(sx[rr][a0], sx[rr][a1]);
        *reinterpret_cast<__half2*>(g_xg + (size_t)(r0 + rr) * C + j) = h;
    }
}

// ---------------------------------------------------------------------------
// Scatter slice: 16 rows [128*band + 16*slot, +16), staged in smem.
// ---------------------------------------------------------------------------
__device__ __forceinline__ void scatter_slice(int band, int slot, char* smem,
                                              const float* __restrict__ x,
                                              const int*   __restrict__ perm,
                                              unsigned mult,
                                              float* __restrict__ out) {
    float (*so)[C] = reinterpret_cast<float (*)[C]>(smem);
    const int tid = threadIdx.x;
    const int r0  = band * BM + slot * 16;

    #pragma unroll
    for (int i = 0; i < 32; i++) {
        int id = tid + i * 256;                 // 0..8191 half2 chunks (16 rows)
        int rr = id >> 9, j = (id & 511) * 2;
        unsigned m = (mult * (unsigned)(r0 + rr) + 1u) & 1023u;
        float2 v = __half22float2(
            *reinterpret_cast<const __half2*>(g_y + (size_t)(r0 + rr) * C + j));
        so[rr][((unsigned)perm[j]     * m) & 1023u] = v.x;
        so[rr][((unsigned)perm[j + 1] * m) & 1023u] = v.y;
    }
    __syncthreads();

    #pragma unroll
    for (int i = 0; i < 16; i++) {
        int id = tid + i * 256;                 // 16 rows x 256 float4
        int rr = id >> 8, j = (id & 255) * 4;
        const size_t off = (size_t)(r0 + rr) * C + j;
        float4 xv = *reinterpret_cast<const float4*>(x + off);
        float4 o;
        o.x = fmaf(so[rr][j],     RAND_SCALE, xv.x);
        o.y = fmaf(so[rr][j + 1], RAND_SCALE, xv.y);
        o.z = fmaf(so[rr][j + 2], RAND_SCALE, xv.z);
        o.w = fmaf(so[rr][j + 3], RAND_SCALE, xv.w);
        *reinterpret_cast<float4*>(out + off) = o;
    }
}

__device__ __forceinline__ void slice_ticket() {
    __syncthreads();
    if (threadIdx.x == 0) {
        int old = atomicAdd(&scnt, 1);
        if (old == TOTAL_SLICES - 1) {
            for (int i = 0; i < NBAND; i++) mcnt[i] = 0;
            scnt = 0;
            __threadfence();
        }
    }
}

// ---------------------------------------------------------------------------
// Launch 2: fused GEMM + lagged scatter.
// ---------------------------------------------------------------------------
__device__ __forceinline__ void fill_stage(int f, int tid, uint32_t smb, int by, int bx) {
    const int s = f % STAGES;
    const uint32_t a_base = smb + s * STAGE_BYTES;
    const uint32_t b_base = a_base + A_SM_BYTES;
    const __half* Ag = g_xg + (size_t)(by * BM) * C + f * BK;
    const __half* Bg = g_uh + (size_t)(f * BK) * C + bx * BN;
    #pragma unroll
    for (int i = 0; i < 4; i++) {
        int id = tid + i * 256;
        int r = id >> 3, c = id & 7;
        cp_async16(a_base + r * 128 + ((c ^ (r & 7)) << 4), Ag + (size_t)r * C + c * 8);
    }
    #pragma unroll
    for (int i = 0; i < 4; i++) {
        int id = tid + i * 256;
        int r = id >> 4, c = id & 15;
        cp_async16(b_base + r * 256 + ((c ^ (r & 7)) << 4), Bg + (size_t)r * C + c * 8);
    }
    asm volatile("cp.async.commit_group;" ::: "memory");
}

__global__ void __launch_bounds__(256, 2)
gemm_scatter_kernel(const float* __restrict__ x,
                    const int*   __restrict__ perm,
                    const int*   __restrict__ randint,
                    float*       __restrict__ out) {
    extern __shared__ char smem[];
    const int tid = threadIdx.x;
    const unsigned mult = ((unsigned)randint[0] * 6u) & 1023u;

    // ---------------- tail scatter blocks ----------------
    if (blockIdx.x >= G_M) {
        const int idx  = blockIdx.x - G_M;        // 0..255
        const int band = (NBAND - LAG) + (idx >> 3);
        const int slot = idx & 7;                 // 8 slots x 16 rows = 128 rows
        spin_until(&mcnt[band], 8);
        scatter_slice(band, slot, smem, x, perm, mult, out);
        slice_ticket();
        return;
    }

    // ---------------- GEMM blocks ----------------
    const int q  = blockIdx.x;
    const int bx = q & 7;
    const int by = q >> 3;
    const uint32_t smb = smem_u32(smem);

    const int wid = tid >> 5, lane = tid & 31;
    const int wm  = wid & 1;
    const int wn  = wid >> 1;
    const int l7   = lane & 7;
    const int seg1 = (lane >> 3) & 1;
    const int seg2 = lane >> 4;

    float acc[4][4][4];
    #pragma unroll
    for (int i = 0; i < 4; i++)
        #pragma unroll
        for (int j = 0; j < 4; j++)
            #pragma unroll
            for (int p = 0; p < 4; p++) acc[i][j][p] = 0.f;

    #pragma unroll
    for (int f = 0; f < STAGES - 1; f++) fill_stage(f, tid, smb, by, bx);

    const int a_rowloc = wm * 64 + l7 + seg1 * 8;
    const int b_kloc   = l7 + seg1 * 8;
    const int b_ccbase = wn * 4 + seg2;

    for (int kt = 0; kt < NKT; kt++) {
        asm volatile("cp.async.wait_group %0;" :: "n"(STAGES - 2) : "memory");
        __syncthreads();

        const int f = kt + STAGES - 1;
        if (f < NKT) fill_stage(f, tid, smb, by, bx);

        const int s = kt % STAGES;
        const uint32_t As = smb + s * STAGE_BYTES;
        const uint32_t Bs = As + A_SM_BYTES;

        #pragma unroll
        for (int ks = 0; ks < 4; ks++) {
            uint32_t afr[4][4], bfr[2][4];
            const int a_chunk = 2 * ks + seg2;
            #pragma unroll
            for (int mt = 0; mt < 4; mt++)
                ldsm_x4(afr[mt], As + (a_rowloc + mt * 16) * 128 + ((a_chunk ^ l7) << 4));
            const int bk = ks * 16 + b_kloc;
            #pragma unroll
            for (int nb = 0; nb < 2; nb++)
                ldsm_x4_t(bfr[nb], Bs + bk * 256 + (((b_ccbase + nb * 2) ^ l7) << 4));
            #pragma unroll
            for (int mt = 0; mt < 4; mt++)
                #pragma unroll
                for (int nt = 0; nt < 4; nt++)
                    mma_f16(acc[mt][nt], afr[mt],
                            bfr[nt >> 1][2 * (nt & 1)], bfr[nt >> 1][2 * (nt & 1) + 1]);
        }
    }

    const int qid = lane >> 2, tq = lane & 3;
    #pragma unroll
    for (int mt = 0; mt < 4; mt++) {
        const int row = by * BM + wm * 64 + mt * 16 + qid;
        #pragma unroll
        for (int nt = 0; nt < 4; nt++) {
            const int col = bx * BN + wn * 32 + nt * 8 + 2 * tq;
            __half* p0 = g_y + (size_t)row * C + col;
            *reinterpret_cast<__half2*>(p0)         = __floats2half2_rn(acc[mt][nt][0], acc[mt][nt][1]);
            *reinterpret_cast<__half2*>(p0 + 8 * C) = __floats2half2_rn(acc[mt][nt][2], acc[mt][nt][3]);
        }
    }
    signal(&mcnt[by]);

    // Lagged scatter: slice bx of band by-LAG (data long since ready).
    if (by >= LAG) {
        const int band = by - LAG;
        spin_until(&mcnt[band], 8);
        scatter_slice(band, bx, smem, x, perm, mult, out);
        slice_ticket();
    }
}

// ---------------------------------------------------------------------------
extern "C" void kernel_launch(void* const* d_in, const int* in_sizes, int n_in,
                              void* d_out, int out_size) {
    const float* x       = (const float*)d_in[0];
    const float* U       = (const float*)d_in[1];
    const int*   perm    = (const int*)d_in[2];
    const int*   randint = (const int*)d_in[3];
    float*       out     = (float*)d_out;

    static bool attr_done = false;
    if (!attr_done) {
        cudaFuncSetAttribute(gemm_scatter_kernel,
                             cudaFuncAttributeMaxDynamicSharedMemorySize, GSMEM);
        attr_done = true;
    }

    gather_uconv_kernel<<<GATHER_BLOCKS + UCONV_BLOCKS, 256>>>(x, U, perm, randint);
    gemm_scatter_kernel<<<GRID2, 256, GSMEM>>>(x, perm, randint, out);
}